// round 17
// baseline (speedup 1.0000x reference)
#include <cuda_runtime.h>
#include <cuda_fp16.h>
#include <math.h>
#include <stdint.h>

#define B_ 2
#define S_ 2048
#define D_ 768
#define H_ 12
#define HD_ 64
#define FF_ 3072
#define L_ 12
#define M_ (B_*S_)   // 4096 rows
#define D3_ (3*D_)   // 2304
#define KS_ 3        // split-K factor for N=768 GEMMs

// ---------------- scratch (device globals; no allocation allowed) ----------
__device__ float g_x[M_*D_];
__device__ float g_p[KS_*M_*D_];                 // split-K partials

__device__ __align__(16) __half g_xh[M_*D_];     // fp16 x (GEMM A input)
__device__ __align__(16) __half g_ah[M_*D_];     // fp16 attention out
__device__ __align__(16) __half g_hh[M_*FF_];    // fp16 gelu out
__device__ __align__(16) __half g_qkv[M_*D3_];   // fused q|k|v rows
// transposed fp16 weights, ALL layers
__device__ __align__(16) __half g_wqkv[L_*D3_*D_];  // [L][2304][768]
__device__ __align__(16) __half g_wo[L_*D_*D_];
__device__ __align__(16) __half g_w1[L_*FF_*D_];    // N=3072,K=768
__device__ __align__(16) __half g_w2[L_*D_*FF_];    // N=768,K=3072
__device__ float g_bqkv[L_*D3_];

// ---------------- PTX helpers (base-target safe) ----------------
__device__ __forceinline__ uint32_t smem_u32(const void* p) {
    uint32_t a;
    asm("{ .reg .u64 t; cvta.to.shared.u64 t, %1; cvt.u32.u64 %0, t; }" : "=r"(a) : "l"(p));
    return a;
}
__device__ __forceinline__ void cp16(uint32_t s, const void* g) {
    asm volatile("cp.async.cg.shared.global [%0], [%1], 16;" :: "r"(s), "l"(g));
}
#define CP_COMMIT()  asm volatile("cp.async.commit_group;" ::: "memory")
#define CP_WAIT(n)   asm volatile("cp.async.wait_group %0;" :: "n"(n) : "memory")

__device__ __forceinline__ void ldm4(uint32_t* r, uint32_t addr) {
    asm volatile("ldmatrix.sync.aligned.m8n8.x4.shared.b16 {%0,%1,%2,%3}, [%4];"
        : "=r"(r[0]), "=r"(r[1]), "=r"(r[2]), "=r"(r[3]) : "r"(addr));
}
__device__ __forceinline__ void ldm4t(uint32_t* r, uint32_t addr) {
    asm volatile("ldmatrix.sync.aligned.m8n8.x4.trans.shared.b16 {%0,%1,%2,%3}, [%4];"
        : "=r"(r[0]), "=r"(r[1]), "=r"(r[2]), "=r"(r[3]) : "r"(addr));
}
__device__ __forceinline__ void mma16816(float* c, const uint32_t* a, uint32_t b0, uint32_t b1) {
    asm volatile("mma.sync.aligned.m16n8k16.row.col.f32.f16.f16.f32 "
        "{%0,%1,%2,%3}, {%4,%5,%6,%7}, {%8,%9}, {%0,%1,%2,%3};"
        : "+f"(c[0]), "+f"(c[1]), "+f"(c[2]), "+f"(c[3])
        : "r"(a[0]), "r"(a[1]), "r"(a[2]), "r"(a[3]), "r"(b0), "r"(b1));
}
__device__ __forceinline__ uint32_t packh2(float a, float b) {
    __half2 h = __floats2half2_rn(a, b);
    return *reinterpret_cast<uint32_t*>(&h);
}

// ---------------- fused weight prep: all transposes in ONE launch ---------
// Segment table passed BY VALUE as a kernel parameter (graph-capture safe).
struct PrepSeg { const float* W; __half* T; int K, N; size_t lsW, lsT; int zbase; };
struct PrepArgs { PrepSeg s[6]; };

__global__ void ttrans_fused(PrepArgs args) {
    __shared__ float t[32][34];
    int z = blockIdx.z;
    int si = 0;
#pragma unroll
    for (int i = 1; i < 6; i++) if (z >= args.s[i].zbase) si = i;
    PrepSeg sg = args.s[si];
    int li = z - sg.zbase;
    int k0 = blockIdx.y * 32, n0 = blockIdx.x * 32;
    if (n0 >= sg.N || k0 >= sg.K) return;
    const float* Wl = sg.W + (size_t)li * sg.lsW;
    __half* Tl = sg.T + (size_t)li * sg.lsT;
    int tx = threadIdx.x & 15, ty = threadIdx.x >> 4;  // 16 x 16, float2 wide
#pragma unroll
    for (int i = 0; i < 2; i++) {
        int kk = ty + i * 16;
        float2 v = *(const float2*)(Wl + (size_t)(k0 + kk) * sg.N + n0 + tx * 2);
        t[kk][tx * 2] = v.x; t[kk][tx * 2 + 1] = v.y;
    }
    __syncthreads();
#pragma unroll
    for (int i = 0; i < 2; i++) {
        int nn = ty + i * 16;
        float a = t[tx * 2][nn], b = t[tx * 2 + 1][nn];
        *(__half2*)(Tl + (size_t)(n0 + nn) * sg.K + k0 + tx * 2) = __floats2half2_rn(a, b);
    }
}

// concat biases: [L][D] x3 -> [L][3D]
__global__ void bcat_kernel(const float* __restrict__ bq, const float* __restrict__ bk,
                            const float* __restrict__ bv) {
    int i = blockIdx.x * blockDim.x + threadIdx.x;
    if (i >= L_ * D3_) return;
    int li = i / D3_, r = i % D3_;
    int sec = r / D_, d = r % D_;
    const float* src = sec == 0 ? bq : (sec == 1 ? bk : bv);
    g_bqkv[i] = src[li * D_ + d];
}

__device__ __forceinline__ float gelu_f(float c) {
    return 0.5f * c * (1.0f + erff(c * 0.70710678118654752f));
}

// ================= GEMM: CTA 256x128, BK=64, 4-stage cp.async =============
#define PITCH   144                // 64 halves (128B) + 16B pad
#define TA      (256*PITCH)        // 36864
#define TB      (128*PITCH)        // 18432
#define STAGE   (TA+TB)            // 55296
#define NSTG    4
#define GSMEM   (NSTG*STAGE)       // 221184

__device__ __forceinline__ void load_chunk(uint32_t sbase,
                                           const __half* pA, const __half* pB,
                                           int K, int tid) {
#pragma unroll
    for (int e = 0; e < 8; e++) {       // A: 256 rows x 8 chunks = 2048
        int idx = tid + e * 256;
        int r = idx >> 3, ch = idx & 7;
        cp16(sbase + r * PITCH + ch * 16, pA + (size_t)r * K + ch * 8);
    }
#pragma unroll
    for (int e = 0; e < 4; e++) {       // B: 128 rows x 8 chunks = 1024
        int idx = tid + e * 256;
        int r = idx >> 3, ch = idx & 7;
        cp16(sbase + TA + r * PITCH + ch * 16, pB + (size_t)r * K + ch * 8);
    }
}

__global__ void __launch_bounds__(256, 1)
gemm_h(const __half* __restrict__ A, const __half* __restrict__ Bt,
       const float* __restrict__ bias,
       void* __restrict__ Cv, int N, int Kfull, int Keff, int epi) {
    extern __shared__ __align__(16) char smem[];
    uint32_t sb = smem_u32(smem);
    int tid = threadIdx.x, wid = tid >> 5, lane = tid & 31;
    int wm = wid >> 1, wn = wid & 1;       // warp tile: 64 x 64
    int m0 = blockIdx.y * 256, n0 = blockIdx.x * 128;
    int z = blockIdx.z;

    const __half* pA = A  + (size_t)m0 * Kfull + (size_t)z * Keff;
    const __half* pB = Bt + (size_t)n0 * Kfull + (size_t)z * Keff;

    float acc[4][8][4] = {};

    const int NC = Keff / 64;
    load_chunk(sb, pA, pB, Kfull, tid);
    CP_COMMIT();
    if (NC > 1) { load_chunk(sb + STAGE, pA + 64, pB + 64, Kfull, tid); CP_COMMIT(); }
    if (NC > 2) { load_chunk(sb + 2*STAGE, pA + 128, pB + 128, Kfull, tid); CP_COMMIT(); }

    int lrow = lane & 15;
    int lch  = (lane >> 4) * 16;

    for (int c = 0; c < NC; c++) {
        int inflight = NC - 1 - c; if (inflight > NSTG - 2) inflight = NSTG - 2;
        if (inflight >= 2)      { CP_WAIT(2); }
        else if (inflight == 1) { CP_WAIT(1); }
        else                    { CP_WAIT(0); }
        __syncthreads();
        if (c + NSTG - 1 < NC) {
            int ns = (c + NSTG - 1) % NSTG;
            load_chunk(sb + ns * STAGE, pA + (c + NSTG - 1) * 64, pB + (c + NSTG - 1) * 64,
                       Kfull, tid);
            CP_COMMIT();
        }
        uint32_t st = sb + (c % NSTG) * STAGE;

#pragma unroll
        for (int ks = 0; ks < 4; ks++) {
            uint32_t ah[4][4], bh[4][4];
#pragma unroll
            for (int mi = 0; mi < 4; mi++) {
                uint32_t off = (uint32_t)(wm*64 + mi*16 + lrow) * PITCH + ks*32 + lch;
                ldm4(ah[mi], st + off);
            }
#pragma unroll
            for (int np = 0; np < 4; np++) {
                uint32_t off = (uint32_t)(wn*64 + np*16 + lrow) * PITCH + ks*32 + lch;
                ldm4(bh[np], st + TA + off);
            }
#pragma unroll
            for (int mi = 0; mi < 4; mi++)
#pragma unroll
                for (int ni = 0; ni < 8; ni++) {
                    int np = ni >> 1, sel = ni & 1;
                    mma16816(acc[mi][ni], ah[mi], bh[np][sel], bh[np][sel + 2]);
                }
        }
    }

    int qrow = lane >> 2, qcol = (lane & 3) * 2;
#pragma unroll
    for (int mi = 0; mi < 4; mi++) {
#pragma unroll
        for (int ni = 0; ni < 8; ni++) {
            int row = m0 + wm*64 + mi*16 + qrow;
            int col = n0 + wn*64 + ni*8 + qcol;
#pragma unroll
            for (int hh = 0; hh < 2; hh++) {
                int r = row + hh * 8;
                float v0 = acc[mi][ni][hh*2 + 0];
                float v1 = acc[mi][ni][hh*2 + 1];
                if (epi == 4) {
                    *(float2*)((float*)Cv + (size_t)z * M_ * N + (size_t)r * N + col) =
                        make_float2(v0, v1);
                } else {
                    v0 += bias[col]; v1 += bias[col + 1];
                    if (epi == 1) { v0 = gelu_f(v0); v1 = gelu_f(v1); }
                    *(__half2*)((__half*)Cv + (size_t)r * N + col) = __floats2half2_rn(v0, v1);
                }
            }
        }
    }
}

// ---------------- reductions ----------------
__device__ __forceinline__ float warp_sum(float v) {
#pragma unroll
    for (int o = 16; o; o >>= 1) v += __shfl_xor_sync(0xffffffffu, v, o);
    return v;
}

// ---------------- fused split-K reduce + residual + bias + LN -------------
__global__ void __launch_bounds__(256)
ln3_kernel(const float* __restrict__ xres, const float* __restrict__ P,
           const float* __restrict__ bias, const float* __restrict__ g,
           const float* __restrict__ b, float* __restrict__ out,
           __half* __restrict__ outh) {
    int wid = threadIdx.x >> 5, lane = threadIdx.x & 31;
    int row = blockIdx.x * 8 + wid;
    const float* r0 = xres + (size_t)row * D_;
    const float* p0 = P + (size_t)row * D_;
    const float* p1 = P + (size_t)M_ * D_ + (size_t)row * D_;
    const float* p2 = P + 2 * (size_t)M_ * D_ + (size_t)row * D_;
    float vals[24];
    float s = 0.f, sq = 0.f;
#pragma unroll
    for (int i = 0; i < 24; i++) {
        int d = lane + i * 32;
        vals[i] = r0[d] + ((p0[d] + p1[d]) + p2[d]) + bias[d];
        s += vals[i]; sq += vals[i] * vals[i];
    }
    s = warp_sum(s); sq = warp_sum(sq);
    float mean = s * (1.0f / D_);
    float var = sq * (1.0f / D_) - mean * mean;
    float inv = rsqrtf(var + 1e-5f);
#pragma unroll
    for (int i = 0; i < 24; i++) {
        int d = lane + i * 32;
        float rr = (vals[i] - mean) * inv * g[d] + b[d];
        out[(size_t)row * D_ + d] = rr;
        outh[(size_t)row * D_ + d] = __float2half(rr);
    }
}

__global__ void __launch_bounds__(256)
embed_ln_kernel(const int* __restrict__ ids, const float* __restrict__ we,
                const float* __restrict__ pe, const float* __restrict__ te,
                const float* __restrict__ g, const float* __restrict__ b) {
    int wid = threadIdx.x >> 5, lane = threadIdx.x & 31;
    int row = blockIdx.x * 8 + wid;
    int s_ = row % S_;
    int id = ids[row];
    float vals[24];
    float s = 0.f, sq = 0.f;
#pragma unroll
    for (int i = 0; i < 24; i++) {
        int d = lane + i * 32;
        vals[i] = we[(size_t)id * D_ + d] + pe[(size_t)(s_ + 2) * D_ + d] + te[d];
        s += vals[i]; sq += vals[i] * vals[i];
    }
    s = warp_sum(s); sq = warp_sum(sq);
    float mean = s * (1.0f / D_);
    float var = sq * (1.0f / D_) - mean * mean;
    float inv = rsqrtf(var + 1e-5f);
#pragma unroll
    for (int i = 0; i < 24; i++) {
        int d = lane + i * 32;
        float rr = (vals[i] - mean) * inv * g[d] + b[d];
        g_x[(size_t)row * D_ + d] = rr;
        g_xh[(size_t)row * D_ + d] = __float2half(rr);
    }
}

// ---------------- tensor-core banded attention ----------------
__global__ void __launch_bounds__(256)
attn_mma(const __half* __restrict__ qkv, const float* __restrict__ mask,
         __half* __restrict__ outh, int half) {
    __shared__ __align__(16) __half qs[128][72];
    __shared__ __align__(16) __half ks[2][32][72];
    __shared__ __align__(16) __half vs[2][32][72];
    __shared__ float kadd[2][32];
    int tid = threadIdx.x, wid = tid >> 5, lane = tid & 31;
    int qt = blockIdx.x * 128;
    int bh = blockIdx.y;
    int b = bh / H_, h = bh % H_;
    const size_t base = (size_t)b * S_;

#pragma unroll
    for (int i = 0; i < 4; i++) {
        int idx = tid + i * 256;
        int r = idx >> 3, seg = idx & 7;
        *(uint4*)&qs[r][seg * 8] =
            *(const uint4*)(qkv + (base + qt + r) * D3_ + h * HD_ + seg * 8);
    }

    int kt0 = qt - half; if (kt0 < 0) kt0 = 0; kt0 >>= 5;
    int kt1 = qt + 127 + half; if (kt1 > S_ - 1) kt1 = S_ - 1; kt1 >>= 5;

    int lr = tid >> 3, lseg = tid & 7;
    {
        const __half* rp = qkv + (base + kt0 * 32 + lr) * D3_ + h * HD_ + lseg * 8;
        *(uint4*)&ks[0][lr][lseg * 8] = *(const uint4*)(rp + D_);
        *(uint4*)&vs[0][lr][lseg * 8] = *(const uint4*)(rp + 2 * D_);
        if (tid < 32) kadd[0][tid] = (1.0f - mask[base + kt0 * 32 + tid]) * -1e9f;
    }
    __syncthreads();

    uint32_t qa[4][4];
    {
        int r = wid * 16 + (lane & 15);
        int cc = (lane >> 4) * 8;
#pragma unroll
        for (int k4 = 0; k4 < 4; k4++)
            ldm4(qa[k4], smem_u32(&qs[r][k4 * 16 + cc]));
    }

    float m0 = -1e30f, m1 = -1e30f, l0 = 0.f, l1 = 0.f;
    float oa[8][4];
#pragma unroll
    for (int t = 0; t < 8; t++) { oa[t][0]=0.f; oa[t][1]=0.f; oa[t][2]=0.f; oa[t][3]=0.f; }

    int qg0 = qt + wid * 16 + (lane >> 2);
    int qg1 = qg0 + 8;
    int kcol = (lane & 3) * 2;
    int qw0 = qt + wid * 16;
    int wlo = qw0 - half, whi = qw0 + 15 + half;

    for (int kt = kt0; kt <= kt1; kt++) {
        int buf = (kt - kt0) & 1;
        int j0 = kt * 32;

        uint4 nk, nv; float nka = 0.f;
        bool more = (kt < kt1);
        if (more) {
            const __half* rp = qkv + (base + (kt+1) * 32 + lr) * D3_ + h * HD_ + lseg * 8;
            nk = *(const uint4*)(rp + D_);
            nv = *(const uint4*)(rp + 2 * D_);
            if (tid < 32) nka = (1.0f - mask[base + (kt+1) * 32 + tid]) * -1e9f;
        }

        if (j0 + 31 >= wlo && j0 <= whi) {
            float sa[4][4] = {};
            {
                int rr = lane & 15, cc = (lane >> 4) * 8;
#pragma unroll
                for (int k4 = 0; k4 < 4; k4++) {
                    uint32_t kb0[4], kb1[4];
                    ldm4(kb0, smem_u32(&ks[buf][rr][k4 * 16 + cc]));
                    ldm4(kb1, smem_u32(&ks[buf][16 + rr][k4 * 16 + cc]));
                    mma16816(sa[0], qa[k4], kb0[0], kb0[2]);
                    mma16816(sa[1], qa[k4], kb0[1], kb0[3]);
                    mma16816(sa[2], qa[k4], kb1[0], kb1[2]);
                    mma16816(sa[3], qa[k4], kb1[1], kb1[3]);
                }
            }

            float mt0 = -1e30f, mt1 = -1e30f;
#pragma unroll
            for (int nt = 0; nt < 4; nt++) {
                float2 ka2 = *(float2*)&kadd[buf][nt * 8 + kcol];
#pragma unroll
                for (int e = 0; e < 2; e++) {
                    int key = j0 + nt * 8 + kcol + e;
                    float ka = e ? ka2.y : ka2.x;
                    float s0 = sa[nt][e] * 0.125f + ka;
                    float s1 = sa[nt][2 + e] * 0.125f + ka;
                    if (key < qg0 - half || key > qg0 + half) s0 = -1e9f;
                    if (key < qg1 - half || key > qg1 + half) s1 = -1e9f;
                    sa[nt][e] = s0; sa[nt][2 + e] = s1;
                    mt0 = fmaxf(mt0, s0); mt1 = fmaxf(mt1, s1);
                }
            }
            mt0 = fmaxf(mt0, __shfl_xor_sync(0xffffffffu, mt0, 1));
            mt0 = fmaxf(mt0, __shfl_xor_sync(0xffffffffu, mt0, 2));
            mt1 = fmaxf(mt1, __shfl_xor_sync(0xffffffffu, mt1, 1));
            mt1 = fmaxf(mt1, __shfl_xor_sync(0xffffffffu, mt1, 2));
            float mn0 = fmaxf(m0, mt0), mn1 = fmaxf(m1, mt1);
            float sc0 = __expf(m0 - mn0), sc1 = __expf(m1 - mn1);
            m0 = mn0; m1 = mn1;

            float ls0 = 0.f, ls1 = 0.f;
            uint32_t pa[2][4];
#pragma unroll
            for (int nt = 0; nt < 4; nt++) {
                float p0 = __expf(sa[nt][0] - mn0);
                float p1 = __expf(sa[nt][1] - mn0);
                float p2 = __expf(sa[nt][2] - mn1);
                float p3 = __expf(sa[nt][3] - mn1);
                ls0 += p0 + p1; ls1 += p2 + p3;
                int kst = nt >> 1, hi = (nt & 1) * 2;
                pa[kst][hi + 0] = packh2(p0, p1);
                pa[kst][hi + 1] = packh2(p2, p3);
            }
            ls0 += __shfl_xor_sync(0xffffffffu, ls0, 1);
            ls0 += __shfl_xor_sync(0xffffffffu, ls0, 2);
            ls1 += __shfl_xor_sync(0xffffffffu, ls1, 1);
            ls1 += __shfl_xor_sync(0xffffffffu, ls1, 2);
            l0 = l0 * sc0 + ls0; l1 = l1 * sc1 + ls1;

#pragma unroll
            for (int t = 0; t < 8; t++) {
                oa[t][0] *= sc0; oa[t][1] *= sc0; oa[t][2] *= sc1; oa[t][3] *= sc1;
            }

            {
                int rr = lane & 15, cc = (lane >> 4) * 8;
#pragma unroll
                for (int kst = 0; kst < 2; kst++) {
#pragma unroll
                    for (int dg = 0; dg < 4; dg++) {
                        uint32_t vb[4];
                        ldm4t(vb, smem_u32(&vs[buf][kst * 16 + rr][dg * 16 + cc]));
                        mma16816(oa[dg * 2],     pa[kst], vb[0], vb[1]);
                        mma16816(oa[dg * 2 + 1], pa[kst], vb[2], vb[3]);
                    }
                }
            }
        }

        if (more) {
            *(uint4*)&ks[buf ^ 1][lr][lseg * 8] = nk;
            *(uint4*)&vs[buf ^ 1][lr][lseg * 8] = nv;
            if (tid < 32) kadd[buf ^ 1][tid] = nka;
        }
        __syncthreads();
    }

    float inv0 = 1.0f / l0, inv1 = 1.0f / l1;
    __half* op0 = outh + (base + qg0) * D_ + h * HD_;
    __half* op1 = outh + (base + qg1) * D_ + h * HD_;
#pragma unroll
    for (int t = 0; t < 8; t++) {
        int dim = t * 8 + kcol;
        *(__half2*)(op0 + dim) = __floats2half2_rn(oa[t][0] * inv0, oa[t][1] * inv0);
        *(__half2*)(op1 + dim) = __floats2half2_rn(oa[t][2] * inv1, oa[t][3] * inv1);
    }
}

// ---------------- top head ----------------
__global__ void top_kernel(const float* __restrict__ fts,
                           const float* __restrict__ Wtop,
                           const float* __restrict__ btop,
                           float* __restrict__ out) {
    int b = blockIdx.x;
    int lane = threadIdx.x & 31, wid = threadIdx.x >> 5;
    __shared__ float sw[8];
    const float* cls = g_x + (size_t)b * S_ * D_;
    float part = 0.f;
    for (int d = threadIdx.x; d < D_; d += 256) part += cls[d] * Wtop[d];
    part = warp_sum(part);
    if (lane == 0) sw[wid] = part;
    __syncthreads();
    if (threadIdx.x == 0) {
        float r = 0.f;
#pragma unroll
        for (int i = 0; i < 8; i++) r += sw[i];
        out[b] = r + fts[b] * Wtop[D_] + btop[0];
    }
}

// ---------------- host driver ----------------
extern "C" void kernel_launch(void* const* d_in, const int* in_sizes, int n_in,
                              void* d_out, int out_size) {
    const int*   ids  = (const int*)  d_in[0];
    const float* mask = (const float*)d_in[1];
    const float* fts  = (const float*)d_in[2];
    const float* we   = (const float*)d_in[3];
    const float* pe   = (const float*)d_in[4];
    const float* te   = (const float*)d_in[5];
    const float* ln_eg= (const float*)d_in[6];
    const float* ln_eb= (const float*)d_in[7];
    const float* Wq   = (const float*)d_in[8];
    const float* bq   = (const float*)d_in[9];
    const float* Wk   = (const float*)d_in[10];
    const float* bk   = (const float*)d_in[11];
    const float* Wv   = (const float*)d_in[12];
    const float* bv   = (const float*)d_in[13];
    const float* Wo   = (const float*)d_in[14];
    const float* bo   = (const float*)d_in[15];
    const float* ln1g = (const float*)d_in[16];
    const float* ln1b = (const float*)d_in[17];
    const float* W1   = (const float*)d_in[18];
    const float* b1   = (const float*)d_in[19];
    const float* W2   = (const float*)d_in[20];
    const float* b2   = (const float*)d_in[21];
    const float* ln2g = (const float*)d_in[22];
    const float* ln2b = (const float*)d_in[23];
    const float* Wtop = (const float*)d_in[24];
    const float* btop = (const float*)d_in[25];
    float* out = (float*)d_out;

    float *x, *pbuf, *bqkv;
    cudaGetSymbolAddress((void**)&x,  g_x);
    cudaGetSymbolAddress((void**)&pbuf, g_p);
    cudaGetSymbolAddress((void**)&bqkv, g_bqkv);

    __half *xh, *ah, *hh, *qkv, *wqkv, *wo, *w1, *w2;
    cudaGetSymbolAddress((void**)&xh, g_xh);
    cudaGetSymbolAddress((void**)&ah, g_ah);
    cudaGetSymbolAddress((void**)&hh, g_hh);
    cudaGetSymbolAddress((void**)&qkv, g_qkv);
    cudaGetSymbolAddress((void**)&wqkv, g_wqkv);
    cudaGetSymbolAddress((void**)&wo, g_wo);
    cudaGetSymbolAddress((void**)&w1, g_w1);
    cudaGetSymbolAddress((void**)&w2, g_w2);

    cudaFuncSetAttribute(gemm_h, cudaFuncAttributeMaxDynamicSharedMemorySize, GSMEM);

    static const int halves[L_] = {16,16,32,32,64,64,128,128,256,256,256,256};

    embed_ln_kernel<<<M_/8, 256>>>(ids, we, pe, te, ln_eg, ln_eb);

    // fused weight prep: one launch, segment table passed by value
    {
        size_t lsD = (size_t)D_ * D_, lsQKV = (size_t)D3_ * D_, lsFF = (size_t)D_ * FF_;
        PrepArgs pa;
        pa.s[0] = { Wq, wqkv + 0 * lsD, D_, D_,  lsD,  lsQKV, 0      };
        pa.s[1] = { Wk, wqkv + 1 * lsD, D_, D_,  lsD,  lsQKV, L_     };
        pa.s[2] = { Wv, wqkv + 2 * lsD, D_, D_,  lsD,  lsQKV, 2 * L_ };
        pa.s[3] = { Wo, wo,             D_, D_,  lsD,  lsD,   3 * L_ };
        pa.s[4] = { W1, w1,             D_, FF_, lsFF, lsFF,  4 * L_ };
        pa.s[5] = { W2, w2,             FF_, D_, lsFF, lsFF,  5 * L_ };
        dim3 gp(FF_ / 32, FF_ / 32, 6 * L_);
        ttrans_fused<<<gp, 256>>>(pa);
    }
    bcat_kernel<<<(L_*D3_ + 255)/256, 256>>>(bq, bk, bv);

    size_t lsD = (size_t)D_ * D_, lsQKV = (size_t)D3_ * D_;
    dim3 gQKV(D3_ / 128, M_ / 256, 1);   // (18, 16) = 288 CTAs
    dim3 gF(FF_ / 128, M_ / 256, 1);     // (24, 16) = 384 CTAs
    dim3 gSK(D_ / 128, M_ / 256, KS_);   // (6, 16, 3) = 288 CTAs split-K
    dim3 ga(S_ / 128, B_ * H_);          // (16, 24) = 384 blocks

    for (int i = 0; i < L_; i++) {
        __half* lwqkv = wqkv + (size_t)i * lsQKV;
        __half* lwo = wo + (size_t)i * lsD;
        __half* lw1 = w1 + (size_t)i * FF_ * D_;
        __half* lw2 = w2 + (size_t)i * D_ * FF_;

        gemm_h<<<gQKV, 256, GSMEM>>>(xh, lwqkv, bqkv + (size_t)i*D3_, qkv, D3_, D_, D_, 3);

        attn_mma<<<ga, 256>>>(qkv, mask, ah, halves[i]);

        // Wo: split-K partials + fused reduce/residual/LN
        gemm_h<<<gSK, 256, GSMEM>>>(ah, lwo, nullptr, pbuf, D_, D_, D_ / KS_, 4);
        ln3_kernel<<<M_/8, 256>>>(x, pbuf, bo + (size_t)i*D_,
                                  ln1g + (size_t)i*D_, ln1b + (size_t)i*D_, x, xh);

        gemm_h<<<gF, 256, GSMEM>>>(xh, lw1, b1 + (size_t)i*FF_, hh, FF_, D_, D_, 1);

        // W2: split-K partials + fused reduce/residual/LN
        gemm_h<<<gSK, 256, GSMEM>>>(hh, lw2, nullptr, pbuf, D_, FF_, FF_ / KS_, 4);
        ln3_kernel<<<M_/8, 256>>>(x, pbuf, b2 + (size_t)i*D_,
                                  ln2g + (size_t)i*D_, ln2b + (size_t)i*D_, x, xh);
    }

    top_kernel<<<B_, 256>>>(fts, Wtop, btop, out);
}